// round 9
// baseline (speedup 1.0000x reference)
#include <cuda_runtime.h>
#include <cuda_fp16.h>
#include <cuda_fp8.h>

// IntDVF: scaling-and-squaring integration of a stationary velocity field.
//   ddf = dvf / 2^7;  repeat 7x: ddf = ddf + warp(ddf, ddf)
// Shapes: (B=2, 128,128,128, 3) float32, trilinear with clamped indices.
//
// R7:
//  - hi field (half4, 8B/vox) lives in a REPLICATE-PADDED 140^3 volume
//    (pad=6 >= max displacement 5.7). Replicated pads are exactly equivalent
//    to index clamping, so gathers need NO integer clamps and use one base
//    index + 8 immediate-offset LDG.64s. A float clamp of loc to [-6,132]
//    (exact, see argument above) guards the pad bound.
//  - lo residual (v - hi) stored as e4m3 fp8, 3 planar bytes/vox, scaled by
//    2^(18-step) to center in e4m3 range. Carry rel err ~2^-15/step.
//  - Working set: hi 87.8 MB + lo 25.2 MB = 113 MB -> fits 126 MB L2.
//  - Pad-fill kernel replicates edges into pads after each producing step.

#define DDIM 128
#define DN   (DDIM * DDIM * DDIM)   // 2097152
#define NBATCH 2
#define NVOX (NBATCH * DN)          // 4194304
#define PAD 6
#define PDIM 140
#define PSLICE (PDIM * PDIM)        // 19600
#define PVOL (PDIM * PDIM * PDIM)   // 2744000
#define NPVOX (NBATCH * PVOL)       // 5488000
#define NTHREADS 256
#define NBLOCKS (NVOX / NTHREADS)   // 16384
#define FILLBLOCKS ((NPVOX + NTHREADS - 1) / NTHREADS)

struct alignas(8) H4 { __half2 xy; __half2 zw; };

__device__ H4            g_hA[NPVOX];
__device__ H4            g_hB[NPVOX];
__device__ unsigned char g_loA[3 * NVOX];   // planes: x @0, y @NVOX, z @2*NVOX
__device__ unsigned char g_loB[3 * NVOX];

__device__ __forceinline__ H4 pack_h4(float x, float y, float z) {
    H4 h;
    h.xy = __floats2half2_rn(x, y);
    h.zw = __floats2half2_rn(z, 0.0f);
    return h;
}

__device__ __forceinline__ unsigned char to_fp8(float f) {
    return (unsigned char)__nv_cvt_float_to_fp8(f, __NV_SATFINITE, __NV_E4M3);
}
__device__ __forceinline__ float from_fp8(unsigned char b) {
    __half_raw hr = __nv_cvt_fp8_to_halfraw((__nv_fp8_storage_t)b, __NV_E4M3);
    return __half2float(*(__half*)&hr);
}

// Write hi (padded layout) + scaled fp8 residual (planar, interior index t).
__device__ __forceinline__ void store_split(H4* hp, unsigned char* lop,
                                            int pidx, int t, float S,
                                            float x, float y, float z) {
    H4 h = pack_h4(x, y, z);
    hp[pidx] = h;
    float2 hxy = __half22float2(h.xy);
    float  hz  = __half2float(__low2half(h.zw));
    lop[t]            = to_fp8((x - hxy.x) * S);
    lop[t + NVOX]     = to_fp8((y - hxy.y) * S);
    lop[t + 2 * NVOX] = to_fp8((z - hz) * S);
}

// dvf (AoS float3) -> scaled hi/lo split into A (interior only; pads filled after)
__global__ __launch_bounds__(NTHREADS) void k_scale_pad(const float* __restrict__ in,
                                                        float S) {
    const float SC = 1.0f / 128.0f;  // 2^-7
    int t = blockIdx.x * NTHREADS + threadIdx.x;       // t < NVOX always
    int b = t >> 21;
    int v = t & (DN - 1);
    int z = v & 127, y = (v >> 7) & 127, x = v >> 14;
    int pidx = b * PVOL + (x + PAD) * PSLICE + (y + PAD) * PDIM + (z + PAD);
    const float* p = in + (size_t)t * 3;
    store_split(g_hA, g_loA, pidx, t, S, p[0] * SC, p[1] * SC, p[2] * SC);
}

// Replicate interior edges into the pad shell of the given buffer.
template <bool BUF_IS_A>
__global__ __launch_bounds__(NTHREADS) void k_fill_pads() {
    H4* __restrict__ h = BUF_IS_A ? g_hA : g_hB;
    int p = blockIdx.x * NTHREADS + threadIdx.x;
    if (p >= NPVOX) return;
    int b = p / PVOL;
    int r = p - b * PVOL;
    int pz = r % PDIM;
    int q  = r / PDIM;
    int py = q % PDIM;
    int px = q / PDIM;
    // interior?
    if (px >= PAD && px < PAD + DDIM &&
        py >= PAD && py < PAD + DDIM &&
        pz >= PAD && pz < PAD + DDIM) return;
    int cx = min(max(px, PAD), PAD + DDIM - 1);
    int cy = min(max(py, PAD), PAD + DDIM - 1);
    int cz = min(max(pz, PAD), PAD + DDIM - 1);
    h[p] = h[b * PVOL + cx * PSLICE + cy * PDIM + cz];
}

// One step: dst = src + trilinear(src_hi, grid + src).
template <bool SRC_IS_A, bool PACK>
__global__ __launch_bounds__(NTHREADS) void k_step(float* __restrict__ out3,
                                                   float invS_in, float S_out) {
    const H4*            __restrict__ hsrc  = SRC_IS_A ? g_hA  : g_hB;
    const unsigned char* __restrict__ losrc = SRC_IS_A ? g_loA : g_loB;
    H4*                  __restrict__ hdst  = SRC_IS_A ? g_hB  : g_hA;
    unsigned char*       __restrict__ lodst = SRC_IS_A ? g_loB : g_loA;

    int t = blockIdx.x * NTHREADS + threadIdx.x;       // t < NVOX always
    int b = t >> 21;
    int v = t & (DN - 1);
    int z = v & 127, y = (v >> 7) & 127, x = v >> 14;

    int pbase = b * PVOL;
    int selfp = pbase + (x + PAD) * PSLICE + (y + PAD) * PDIM + (z + PAD);

    // Self-read: carry = hi + lo * invS
    H4 hself = hsrc[selfp];
    float2 hxy = __half22float2(hself.xy);
    float  hz  = __half2float(__low2half(hself.zw));
    float dx = fmaf(from_fp8(losrc[t]),            invS_in, hxy.x);
    float dy = fmaf(from_fp8(losrc[t + NVOX]),     invS_in, hxy.y);
    float dz = fmaf(from_fp8(losrc[t + 2 * NVOX]), invS_in, hz);

    float lx = (float)x + dx;
    float ly = (float)y + dy;
    float lz = (float)z + dz;

    // Safety clamp; exact vs reference (pads replicate edge values).
    lx = fminf(fmaxf(lx, -6.0f), 132.0f);
    ly = fminf(fmaxf(ly, -6.0f), 132.0f);
    lz = fminf(fmaxf(lz, -6.0f), 132.0f);

    float fx = floorf(lx), fy = floorf(ly), fz = floorf(lz);
    float wx1 = lx - fx, wy1 = ly - fy, wz1 = lz - fz;
    float wx0 = 1.0f - wx1, wy0 = 1.0f - wy1, wz0 = 1.0f - wz1;

    int jx = (int)fx, jy = (int)fy, jz = (int)fz;
    // padded corner base; no clamps needed
    const H4* __restrict__ cp = hsrc + (pbase
        + (jx + PAD) * PSLICE + (jy + PAD) * PDIM + (jz + PAD));

    // 8 corner fetches: one base address, immediate offsets.
    H4 c000 = cp[0];
    H4 c001 = cp[1];
    H4 c010 = cp[PDIM];
    H4 c011 = cp[PDIM + 1];
    H4 c100 = cp[PSLICE];
    H4 c101 = cp[PSLICE + 1];
    H4 c110 = cp[PSLICE + PDIM];
    H4 c111 = cp[PSLICE + PDIM + 1];

    float w00 = wx0 * wy0;
    float w01 = wx0 * wy1;
    float w10 = wx1 * wy0;
    float w11 = wx1 * wy1;

    float w000 = w00 * wz0, w001 = w00 * wz1;
    float w010 = w01 * wz0, w011 = w01 * wz1;
    float w100 = w10 * wz0, w101 = w10 * wz1;
    float w110 = w11 * wz0, w111 = w11 * wz1;

    float ax = dx, ay = dy, az = dz;
    #define ACC(W, C) do {                                   \
        float2 _xy = __half22float2((C).xy);                 \
        float  _z  = __half2float(__low2half((C).zw));       \
        ax = fmaf((W), _xy.x, ax);                           \
        ay = fmaf((W), _xy.y, ay);                           \
        az = fmaf((W), _z,    az);                           \
    } while (0)

    ACC(w000, c000); ACC(w001, c001);
    ACC(w010, c010); ACC(w011, c011);
    ACC(w100, c100); ACC(w101, c101);
    ACC(w110, c110); ACC(w111, c111);
    #undef ACC

    if (PACK) {
        float* q = out3 + (size_t)t * 3;
        q[0] = ax; q[1] = ay; q[2] = az;
    } else {
        store_split(hdst, lodst, selfp - pbase + b * PVOL, t, S_out, ax, ay, az);
    }
}

extern "C" void kernel_launch(void* const* d_in, const int* in_sizes, int n_in,
                              void* d_out, int out_size) {
    const float* dvf = (const float*)d_in[0];
    float* out = (float*)d_out;

    // Per-step fp8 residual scales: field magnitude ~2^(i-7) after i steps,
    // residual ~2^-11 of that -> scale 2^(18-i) centers it in e4m3 range.
    float S[8];
    for (int i = 0; i < 8; i++) S[i] = ldexpf(1.0f, 18 - i);

    // ddf0 (i=0) into A, then fill A's pads.
    k_scale_pad<<<NBLOCKS, NTHREADS>>>(dvf, S[0]);
    k_fill_pads<true><<<FILLBLOCKS, NTHREADS>>>();

    // Steps 1..6: ping-pong with pad fills. Step 7 packs to d_out.
    k_step<true,  false><<<NBLOCKS, NTHREADS>>>(nullptr, 1.0f / S[0], S[1]); // A->B
    k_fill_pads<false><<<FILLBLOCKS, NTHREADS>>>();
    k_step<false, false><<<NBLOCKS, NTHREADS>>>(nullptr, 1.0f / S[1], S[2]); // B->A
    k_fill_pads<true><<<FILLBLOCKS, NTHREADS>>>();
    k_step<true,  false><<<NBLOCKS, NTHREADS>>>(nullptr, 1.0f / S[2], S[3]); // A->B
    k_fill_pads<false><<<FILLBLOCKS, NTHREADS>>>();
    k_step<false, false><<<NBLOCKS, NTHREADS>>>(nullptr, 1.0f / S[3], S[4]); // B->A
    k_fill_pads<true><<<FILLBLOCKS, NTHREADS>>>();
    k_step<true,  false><<<NBLOCKS, NTHREADS>>>(nullptr, 1.0f / S[4], S[5]); // A->B
    k_fill_pads<false><<<FILLBLOCKS, NTHREADS>>>();
    k_step<false, false><<<NBLOCKS, NTHREADS>>>(nullptr, 1.0f / S[5], S[6]); // B->A
    k_fill_pads<true><<<FILLBLOCKS, NTHREADS>>>();
    k_step<true,  true ><<<NBLOCKS, NTHREADS>>>(out, 1.0f / S[6], 0.0f);     // A->out
}

// round 10
// speedup vs baseline: 1.5642x; 1.5642x over previous
#include <cuda_runtime.h>
#include <cuda_fp16.h>
#include <cuda_fp8.h>

// IntDVF: scaling-and-squaring integration of a stationary velocity field.
//   ddf = dvf / 2^7;  repeat 7x: ddf = ddf + warp(ddf, ddf)
// Shapes: (B=2, 128,128,128, 3) float32, trilinear with clamped indices.
//
// R9 = R6 structure (best: 248.9us) + fp8 lo residual from R7 (verified
// identical rel_err), NO padded volume / NO fill kernels (R7's 107us
// overhead + slower step made it a net loss).
//   hi = half4 (8B/vox): gather shadow AND self-read high part.
//   lo = e4m3 residual (v - hi), 3 planar bytes/vox, scaled 2^(18-i):
//        carry rel err ~2^-15/step, invisible next to the 2^-11 hi gathers.
// Footprint: hi 2x33.5 + lo 2x12.6 = 92 MB << 126 MB L2 -> streaming dst
// no longer evicts src; DRAM stalls should mostly vanish.

#define DDIM 128
#define DN   (DDIM * DDIM * DDIM)   // 2097152
#define NBATCH 2
#define NVOX (NBATCH * DN)          // 4194304
#define NTHREADS 256
#define NBLOCKS (NVOX / NTHREADS)   // 16384

struct alignas(8) H4 { __half2 xy; __half2 zw; };

__device__ H4            g_hA[NVOX];
__device__ H4            g_hB[NVOX];
__device__ unsigned char g_loA[3 * NVOX];   // planes: x @0, y @NVOX, z @2*NVOX
__device__ unsigned char g_loB[3 * NVOX];

__device__ __forceinline__ H4 pack_h4(float x, float y, float z) {
    H4 h;
    h.xy = __floats2half2_rn(x, y);
    h.zw = __floats2half2_rn(z, 0.0f);
    return h;
}

__device__ __forceinline__ unsigned char to_fp8(float f) {
    return (unsigned char)__nv_cvt_float_to_fp8(f, __NV_SATFINITE, __NV_E4M3);
}
__device__ __forceinline__ float from_fp8(unsigned char b) {
    __half_raw hr = __nv_cvt_fp8_to_halfraw((__nv_fp8_storage_t)b, __NV_E4M3);
    return __half2float(*(__half*)&hr);
}

// Write hi + scaled fp8 residual.
__device__ __forceinline__ void store_split(H4* hp, unsigned char* lop,
                                            int t, float S,
                                            float x, float y, float z) {
    H4 h = pack_h4(x, y, z);
    hp[t] = h;
    float2 hxy = __half22float2(h.xy);
    float  hz  = __half2float(__low2half(h.zw));
    lop[t]            = to_fp8((x - hxy.x) * S);
    lop[t + NVOX]     = to_fp8((y - hxy.y) * S);
    lop[t + 2 * NVOX] = to_fp8((z - hz) * S);
}

// dvf (AoS float3) -> scaled hi/lo split into A
__global__ __launch_bounds__(NTHREADS) void k_scale_pad(const float* __restrict__ in,
                                                        float S) {
    const float SC = 1.0f / 128.0f;  // 2^-7
    int t = blockIdx.x * NTHREADS + threadIdx.x;       // t < NVOX always
    const float* p = in + (size_t)t * 3;
    store_split(g_hA, g_loA, t, S, p[0] * SC, p[1] * SC, p[2] * SC);
}

// One step: dst = src + trilinear(src_hi, grid + src).
template <bool SRC_IS_A, bool PACK>
__global__ __launch_bounds__(NTHREADS) void k_step(float* __restrict__ out3,
                                                   float invS_in, float S_out) {
    const H4*            __restrict__ hsrc  = SRC_IS_A ? g_hA  : g_hB;
    const unsigned char* __restrict__ losrc = SRC_IS_A ? g_loA : g_loB;
    H4*                  __restrict__ hdst  = SRC_IS_A ? g_hB  : g_hA;
    unsigned char*       __restrict__ lodst = SRC_IS_A ? g_loB : g_loA;

    int t = blockIdx.x * NTHREADS + threadIdx.x;       // t < NVOX always
    int b = t >> 21;                                   // DN = 2^21
    int v = t & (DN - 1);
    int z = v & 127;
    int y = (v >> 7) & 127;
    int x = v >> 14;

    const H4* __restrict__ hb = hsrc + (size_t)b * DN;

    // Self-read: carry = hi + lo * invS  (issue all loads up front for MLP)
    H4 hself = hsrc[t];
    unsigned char l0 = losrc[t];
    unsigned char l1 = losrc[t + NVOX];
    unsigned char l2 = losrc[t + 2 * NVOX];
    float2 hxy = __half22float2(hself.xy);
    float  hz  = __half2float(__low2half(hself.zw));
    float dx = fmaf(from_fp8(l0), invS_in, hxy.x);
    float dy = fmaf(from_fp8(l1), invS_in, hxy.y);
    float dz = fmaf(from_fp8(l2), invS_in, hz);

    float lx = (float)x + dx;
    float ly = (float)y + dy;
    float lz = (float)z + dz;

    float fx = floorf(lx), fy = floorf(ly), fz = floorf(lz);
    float wx1 = lx - fx, wy1 = ly - fy, wz1 = lz - fz;
    float wx0 = 1.0f - wx1, wy0 = 1.0f - wy1, wz0 = 1.0f - wz1;

    int jx = (int)fx, jy = (int)fy, jz = (int)fz;
    int ix0 = min(max(jx, 0), 127);
    int ix1 = min(max(jx + 1, 0), 127);
    int iy0 = min(max(jy, 0), 127);
    int iy1 = min(max(jy + 1, 0), 127);
    int iz0 = min(max(jz, 0), 127);
    int iz1 = min(max(jz + 1, 0), 127);

    int X0 = ix0 << 14, X1 = ix1 << 14;
    int Y0 = iy0 << 7,  Y1 = iy1 << 7;

    // 8 corner fetches from the fp16 hi field (one LDG.64 each).
    H4 c000 = hb[X0 + Y0 + iz0];
    H4 c001 = hb[X0 + Y0 + iz1];
    H4 c010 = hb[X0 + Y1 + iz0];
    H4 c011 = hb[X0 + Y1 + iz1];
    H4 c100 = hb[X1 + Y0 + iz0];
    H4 c101 = hb[X1 + Y0 + iz1];
    H4 c110 = hb[X1 + Y1 + iz0];
    H4 c111 = hb[X1 + Y1 + iz1];

    float w00 = wx0 * wy0;
    float w01 = wx0 * wy1;
    float w10 = wx1 * wy0;
    float w11 = wx1 * wy1;

    float w000 = w00 * wz0, w001 = w00 * wz1;
    float w010 = w01 * wz0, w011 = w01 * wz1;
    float w100 = w10 * wz0, w101 = w10 * wz1;
    float w110 = w11 * wz0, w111 = w11 * wz1;

    float ax = dx, ay = dy, az = dz;
    #define ACC(W, C) do {                                   \
        float2 _xy = __half22float2((C).xy);                 \
        float  _z  = __half2float(__low2half((C).zw));       \
        ax = fmaf((W), _xy.x, ax);                           \
        ay = fmaf((W), _xy.y, ay);                           \
        az = fmaf((W), _z,    az);                           \
    } while (0)

    ACC(w000, c000); ACC(w001, c001);
    ACC(w010, c010); ACC(w011, c011);
    ACC(w100, c100); ACC(w101, c101);
    ACC(w110, c110); ACC(w111, c111);
    #undef ACC

    if (PACK) {
        float* q = out3 + (size_t)t * 3;
        q[0] = ax; q[1] = ay; q[2] = az;
    } else {
        store_split(hdst, lodst, t, S_out, ax, ay, az);
    }
}

extern "C" void kernel_launch(void* const* d_in, const int* in_sizes, int n_in,
                              void* d_out, int out_size) {
    const float* dvf = (const float*)d_in[0];
    float* out = (float*)d_out;

    // Per-step fp8 residual scales: field magnitude ~2^(i-7) after i steps,
    // residual ~2^-11 of that -> scale 2^(18-i) centers it in e4m3 range.
    float S[8];
    for (int i = 0; i < 8; i++) S[i] = ldexpf(1.0f, 18 - i);

    // ddf0 (i=0) into A.
    k_scale_pad<<<NBLOCKS, NTHREADS>>>(dvf, S[0]);

    // 7 squaring steps, ping-pong A<->B; final step writes float3 to d_out.
    k_step<true,  false><<<NBLOCKS, NTHREADS>>>(nullptr, 1.0f / S[0], S[1]); // A->B
    k_step<false, false><<<NBLOCKS, NTHREADS>>>(nullptr, 1.0f / S[1], S[2]); // B->A
    k_step<true,  false><<<NBLOCKS, NTHREADS>>>(nullptr, 1.0f / S[2], S[3]); // A->B
    k_step<false, false><<<NBLOCKS, NTHREADS>>>(nullptr, 1.0f / S[3], S[4]); // B->A
    k_step<true,  false><<<NBLOCKS, NTHREADS>>>(nullptr, 1.0f / S[4], S[5]); // A->B
    k_step<false, false><<<NBLOCKS, NTHREADS>>>(nullptr, 1.0f / S[5], S[6]); // B->A
    k_step<true,  true ><<<NBLOCKS, NTHREADS>>>(out, 1.0f / S[6], 0.0f);     // A->out
}

// round 13
// speedup vs baseline: 1.6085x; 1.0283x over previous
#include <cuda_runtime.h>
#include <cuda_fp16.h>
#include <cuda_fp8.h>

// IntDVF: scaling-and-squaring integration of a stationary velocity field.
//   ddf = dvf / 2^7;  repeat 7x: ddf = ddf + warp(ddf, ddf)
// Shapes: (B=2, 128,128,128, 3) float32, trilinear with clamped indices.
//
// R10 was issue-bound (issue 65%, fma+alu 67%). R11 cuts instructions:
//  - half2-packed interpolation: corners stay in __half2 regs, weights are
//    F2FP-broadcast once, 2 HFMA2 per corner (was 3 cvt + 3 FFMA).
//    Adds ~2^-11 fp16 accumulation rounding (same order as existing hi
//    quantization) -> expected rel_err ~3e-4 (< 1e-3 gate).
//  - lo residual now ONE interleaved uchar4 (4B/vox): 1 LDG.32 / 1 STG.32
//    instead of 3 scalar byte ops each way, with hw fp8x2<->half2 converts.
// Carry remains hi(fp16) + lo(e4m3, scaled 2^(18-i)) = ~2^-15 per-step carry
// error. Footprint: hi 67 MB + lo 33.5 MB = 100 MB < 126 MB L2.

#define DDIM 128
#define DN   (DDIM * DDIM * DDIM)   // 2097152
#define NBATCH 2
#define NVOX (NBATCH * DN)          // 4194304
#define NTHREADS 256
#define NBLOCKS (NVOX / NTHREADS)   // 16384

struct alignas(8) H4 { __half2 xy; __half2 zw; };

__device__ H4           g_hA[NVOX];
__device__ H4           g_hB[NVOX];
__device__ unsigned int g_loA[NVOX];   // uchar4: e4m3 x,y,z residuals + pad
__device__ unsigned int g_loB[NVOX];

__device__ __forceinline__ H4 pack_h4(float x, float y, float z) {
    H4 h;
    h.xy = __floats2half2_rn(x, y);
    h.zw = __floats2half2_rn(z, 0.0f);
    return h;
}

// Pack 3 scaled residuals into one uchar4 word (e4m3 x2 + e4m3).
__device__ __forceinline__ unsigned int pack_lo(float rx, float ry, float rz) {
    __nv_fp8x2_storage_t b01 =
        __nv_cvt_float2_to_fp8x2(make_float2(rx, ry), __NV_SATFINITE, __NV_E4M3);
    __nv_fp8_storage_t b2 =
        __nv_cvt_float_to_fp8(rz, __NV_SATFINITE, __NV_E4M3);
    return (unsigned int)b01 | ((unsigned int)b2 << 16);
}

// Write hi + scaled fp8 residual word.
__device__ __forceinline__ void store_split(H4* hp, unsigned int* lop,
                                            int t, float S,
                                            float x, float y, float z) {
    H4 h = pack_h4(x, y, z);
    hp[t] = h;
    float2 hxy = __half22float2(h.xy);
    float  hz  = __half2float(__low2half(h.zw));
    lop[t] = pack_lo((x - hxy.x) * S, (y - hxy.y) * S, (z - hz) * S);
}

// dvf (AoS float3) -> scaled hi/lo split into A
__global__ __launch_bounds__(NTHREADS) void k_scale_pad(const float* __restrict__ in,
                                                        float S) {
    const float SC = 1.0f / 128.0f;  // 2^-7
    int t = blockIdx.x * NTHREADS + threadIdx.x;       // t < NVOX always
    const float* p = in + (size_t)t * 3;
    store_split(g_hA, g_loA, t, S, p[0] * SC, p[1] * SC, p[2] * SC);
}

// One step: dst = src + trilinear(src_hi, grid + src).
template <bool SRC_IS_A, bool PACK>
__global__ __launch_bounds__(NTHREADS) void k_step(float* __restrict__ out3,
                                                   float invS_in, float S_out) {
    const H4*           __restrict__ hsrc  = SRC_IS_A ? g_hA  : g_hB;
    const unsigned int* __restrict__ losrc = SRC_IS_A ? g_loA : g_loB;
    H4*                 __restrict__ hdst  = SRC_IS_A ? g_hB  : g_hA;
    unsigned int*       __restrict__ lodst = SRC_IS_A ? g_loB : g_loA;

    int t = blockIdx.x * NTHREADS + threadIdx.x;       // t < NVOX always
    int b = t >> 21;                                   // DN = 2^21
    int v = t & (DN - 1);
    int z = v & 127;
    int y = (v >> 7) & 127;
    int x = v >> 14;

    const H4* __restrict__ hb = hsrc + (size_t)b * DN;

    // Self-read: carry = hi + lo * invS
    H4 hself = hsrc[t];
    unsigned int lw = losrc[t];
    __half2_raw h01r = __nv_cvt_fp8x2_to_halfraw2(
        (__nv_fp8x2_storage_t)(lw & 0xFFFFu), __NV_E4M3);
    __half_raw h2r = __nv_cvt_fp8_to_halfraw(
        (__nv_fp8_storage_t)((lw >> 16) & 0xFFu), __NV_E4M3);
    __half2 l01 = *(__half2*)&h01r;
    float2 lo01 = __half22float2(l01);
    float  lo2  = __half2float(*(__half*)&h2r);

    float2 hxy = __half22float2(hself.xy);
    float  hz  = __half2float(__low2half(hself.zw));
    float dx = fmaf(lo01.x, invS_in, hxy.x);
    float dy = fmaf(lo01.y, invS_in, hxy.y);
    float dz = fmaf(lo2,    invS_in, hz);

    float lx = (float)x + dx;
    float ly = (float)y + dy;
    float lz = (float)z + dz;

    float fx = floorf(lx), fy = floorf(ly), fz = floorf(lz);
    float wx1 = lx - fx, wy1 = ly - fy, wz1 = lz - fz;
    float wx0 = 1.0f - wx1, wy0 = 1.0f - wy1, wz0 = 1.0f - wz1;

    int jx = (int)fx, jy = (int)fy, jz = (int)fz;
    int ix0 = min(max(jx, 0), 127);
    int ix1 = min(max(jx + 1, 0), 127);
    int iy0 = min(max(jy, 0), 127);
    int iy1 = min(max(jy + 1, 0), 127);
    int iz0 = min(max(jz, 0), 127);
    int iz1 = min(max(jz + 1, 0), 127);

    int X0 = ix0 << 14, X1 = ix1 << 14;
    int Y0 = iy0 << 7,  Y1 = iy1 << 7;

    // 8 corner fetches from the fp16 hi field (one LDG.64 each).
    H4 c000 = hb[X0 + Y0 + iz0];
    H4 c001 = hb[X0 + Y0 + iz1];
    H4 c010 = hb[X0 + Y1 + iz0];
    H4 c011 = hb[X0 + Y1 + iz1];
    H4 c100 = hb[X1 + Y0 + iz0];
    H4 c101 = hb[X1 + Y0 + iz1];
    H4 c110 = hb[X1 + Y1 + iz0];
    H4 c111 = hb[X1 + Y1 + iz1];

    float w00 = wx0 * wy0;
    float w01 = wx0 * wy1;
    float w10 = wx1 * wy0;
    float w11 = wx1 * wy1;

    float w000 = w00 * wz0, w001 = w00 * wz1;
    float w010 = w01 * wz0, w011 = w01 * wz1;
    float w100 = w10 * wz0, w101 = w10 * wz1;
    float w110 = w11 * wz0, w111 = w11 * wz1;

    // half2-packed accumulation: 2 HFMA2 per corner.
    __half2 acc_xy = __floats2half2_rn(0.0f, 0.0f);
    __half2 acc_z  = acc_xy;
    #define ACC(W, C) do {                                   \
        __half2 _w2 = __floats2half2_rn((W), (W));           \
        acc_xy = __hfma2(_w2, (C).xy, acc_xy);               \
        acc_z  = __hfma2(_w2, (C).zw, acc_z);                \
    } while (0)

    ACC(w000, c000); ACC(w001, c001);
    ACC(w010, c010); ACC(w011, c011);
    ACC(w100, c100); ACC(w101, c101);
    ACC(w110, c110); ACC(w111, c111);
    #undef ACC

    float2 ixy = __half22float2(acc_xy);
    float  iz  = __half2float(__low2half(acc_z));
    float ax = dx + ixy.x;
    float ay = dy + ixy.y;
    float az = dz + iz;

    if (PACK) {
        float* q = out3 + (size_t)t * 3;
        q[0] = ax; q[1] = ay; q[2] = az;
    } else {
        store_split(hdst, lodst, t, S_out, ax, ay, az);
    }
}

extern "C" void kernel_launch(void* const* d_in, const int* in_sizes, int n_in,
                              void* d_out, int out_size) {
    const float* dvf = (const float*)d_in[0];
    float* out = (float*)d_out;

    // Per-step fp8 residual scales: field magnitude ~2^(i-7) after i steps,
    // residual ~2^-11 of that -> scale 2^(18-i) centers it in e4m3 range.
    float S[8];
    for (int i = 0; i < 8; i++) S[i] = ldexpf(1.0f, 18 - i);

    // ddf0 (i=0) into A.
    k_scale_pad<<<NBLOCKS, NTHREADS>>>(dvf, S[0]);

    // 7 squaring steps, ping-pong A<->B; final step writes float3 to d_out.
    k_step<true,  false><<<NBLOCKS, NTHREADS>>>(nullptr, 1.0f / S[0], S[1]); // A->B
    k_step<false, false><<<NBLOCKS, NTHREADS>>>(nullptr, 1.0f / S[1], S[2]); // B->A
    k_step<true,  false><<<NBLOCKS, NTHREADS>>>(nullptr, 1.0f / S[2], S[3]); // A->B
    k_step<false, false><<<NBLOCKS, NTHREADS>>>(nullptr, 1.0f / S[3], S[4]); // B->A
    k_step<true,  false><<<NBLOCKS, NTHREADS>>>(nullptr, 1.0f / S[4], S[5]); // A->B
    k_step<false, false><<<NBLOCKS, NTHREADS>>>(nullptr, 1.0f / S[5], S[6]); // B->A
    k_step<true,  true ><<<NBLOCKS, NTHREADS>>>(out, 1.0f / S[6], 0.0f);     // A->out
}